// round 2
// baseline (speedup 1.0000x reference)
#include <cuda_runtime.h>
#include <math.h>

#define S_    2048
#define H_    2048
#define NH_   32
#define KVH_  8
#define D_    64
#define QKVC  3072   // (NH + 2*KVH) * D

__device__ float g_qkv[S_ * QKVC];   // 24 MiB scratch
__device__ float g_attn[S_ * H_];    // 16 MiB scratch

// ---------------------------------------------------------------------------
// NT GEMM: C[M,N] = A[M,K] @ B[N,K]^T   (both operands K-major, row-major)
// 128x128 block tile, BK=16, 256 threads, 8x8 per-thread microtile.
// ---------------------------------------------------------------------------
__global__ __launch_bounds__(256, 2)
void gemm_nt(const float* __restrict__ A, const float* __restrict__ B,
             float* __restrict__ C, int M, int N, int K)
{
    __shared__ float As[16][128];
    __shared__ float Bs[16][128];

    const int tid = threadIdx.x;
    const int tx  = tid & 15;
    const int ty  = tid >> 4;
    const int m0  = blockIdx.y * 128;
    const int n0  = blockIdx.x * 128;

    const int lr = tid >> 2;          // 0..63
    const int lc = (tid & 3) << 2;    // 0,4,8,12

    float acc[8][8];
#pragma unroll
    for (int i = 0; i < 8; i++)
#pragma unroll
        for (int j = 0; j < 8; j++) acc[i][j] = 0.f;

    const float* Ap = A + (size_t)(m0 + lr) * K + lc;
    const float* Bp = B + (size_t)(n0 + lr) * K + lc;

    for (int k0 = 0; k0 < K; k0 += 16) {
        float4 a0 = *(const float4*)(Ap + k0);
        float4 a1 = *(const float4*)(Ap + (size_t)64 * K + k0);
        float4 b0 = *(const float4*)(Bp + k0);
        float4 b1 = *(const float4*)(Bp + (size_t)64 * K + k0);

        As[lc + 0][lr]      = a0.x; As[lc + 1][lr]      = a0.y;
        As[lc + 2][lr]      = a0.z; As[lc + 3][lr]      = a0.w;
        As[lc + 0][lr + 64] = a1.x; As[lc + 1][lr + 64] = a1.y;
        As[lc + 2][lr + 64] = a1.z; As[lc + 3][lr + 64] = a1.w;

        Bs[lc + 0][lr]      = b0.x; Bs[lc + 1][lr]      = b0.y;
        Bs[lc + 2][lr]      = b0.z; Bs[lc + 3][lr]      = b0.w;
        Bs[lc + 0][lr + 64] = b1.x; Bs[lc + 1][lr + 64] = b1.y;
        Bs[lc + 2][lr + 64] = b1.z; Bs[lc + 3][lr + 64] = b1.w;

        __syncthreads();

#pragma unroll
        for (int kk = 0; kk < 16; kk++) {
            float a[8], b[8];
            *(float4*)&a[0] = *(const float4*)&As[kk][ty * 4];
            *(float4*)&a[4] = *(const float4*)&As[kk][64 + ty * 4];
            *(float4*)&b[0] = *(const float4*)&Bs[kk][tx * 4];
            *(float4*)&b[4] = *(const float4*)&Bs[kk][64 + tx * 4];
#pragma unroll
            for (int i = 0; i < 8; i++)
#pragma unroll
                for (int j = 0; j < 8; j++)
                    acc[i][j] = fmaf(a[i], b[j], acc[i][j]);
        }
        __syncthreads();
    }

#pragma unroll
    for (int ih = 0; ih < 2; ih++)
#pragma unroll
        for (int i = 0; i < 4; i++) {
            int row = m0 + ih * 64 + ty * 4 + i;
            float* Cp = C + (size_t)row * N + n0;
            int ai = ih * 4 + i;
            *(float4*)(Cp + tx * 4) =
                make_float4(acc[ai][0], acc[ai][1], acc[ai][2], acc[ai][3]);
            *(float4*)(Cp + 64 + tx * 4) =
                make_float4(acc[ai][4], acc[ai][5], acc[ai][6], acc[ai][7]);
        }
}

// ---------------------------------------------------------------------------
// RoPE in-place on q (32 heads) and k (8 heads) columns of the qkv buffer.
// ---------------------------------------------------------------------------
__global__ void rope_kernel(float* __restrict__ qkv)
{
    int idx = blockIdx.x * blockDim.x + threadIdx.x;
    const int total = S_ * (NH_ + KVH_) * 32;
    if (idx >= total) return;

    int i  = idx & 31;
    int hh = (idx >> 5) % (NH_ + KVH_);
    int s  = idx / ((NH_ + KVH_) * 32);
    int col = (hh < NH_) ? hh * 64 : NH_ * 64 + (hh - NH_) * 64;

    float inv_freq = powf(10000.0f, -(float)i / 32.0f);
    float fr = (float)s * inv_freq;
    float sn, c;
    sincosf(fr, &sn, &c);

    float* base = qkv + (size_t)s * QKVC + col;
    float x1 = base[i];
    float x2 = base[i + 32];
    base[i]      = x1 * c - x2 * sn;
    base[i + 32] = x2 * c + x1 * sn;
}

// ---------------------------------------------------------------------------
// Flash-style causal GQA attention.
// Grid: (NH heads, S/64 query tiles). Block: 256 threads.
// Thread (rg = tid/16, cl = tid%16) owns score microtile:
//   rows r0..r0+3 (r0 = rg*4), keys {cl + 16j}, output dims {cl*4 + jj}.
// Smem tiles padded to stride 68 (bank-conflict-free row access).
// P tile aliases the K tile.
// ---------------------------------------------------------------------------
__global__ __launch_bounds__(256)
void attn_kernel(const float* __restrict__ qkv, float* __restrict__ outp)
{
    constexpr int ST = 68;
    extern __shared__ float sm[];
    float* Qs = sm;
    float* Ks = sm + 64 * ST;
    float* Vs = sm + 2 * 64 * ST;
    float* Ps = Ks;  // alias

    const int h   = blockIdx.x;
    const int qt  = blockIdx.y;
    const int tid = threadIdx.x;
    const int rg  = tid >> 4;
    const int cl  = tid & 15;
    const int r0  = rg * 4;
    const int kvh = h >> 2;

    const int qcol = h * 64;
    const int kcol = NH_ * 64 + kvh * 64;
    const int vcol = NH_ * 64 + KVH_ * 64 + kvh * 64;

    // Load Q tile (pre-scaled by 1/sqrt(D))
    {
        const float scale = 0.125f;
#pragma unroll
        for (int p = 0; p < 4; p++) {
            int idx = tid + p * 256;
            int row = idx >> 4;
            int c4  = (idx & 15) << 2;
            float4 v = *(const float4*)&qkv[(size_t)(qt * 64 + row) * QKVC + qcol + c4];
            float* dst = &Qs[row * ST + c4];
            dst[0] = v.x * scale; dst[1] = v.y * scale;
            dst[2] = v.z * scale; dst[3] = v.w * scale;
        }
    }

    float m[4], l[4], o[4][4];
#pragma unroll
    for (int i = 0; i < 4; i++) {
        m[i] = -INFINITY; l[i] = 0.f;
#pragma unroll
        for (int j = 0; j < 4; j++) o[i][j] = 0.f;
    }

    for (int kt = 0; kt <= qt; kt++) {
        __syncthreads();  // previous iter done reading Ks(=Ps)/Vs; Q visible on iter 0
#pragma unroll
        for (int p = 0; p < 4; p++) {
            int idx = tid + p * 256;
            int row = idx >> 4;
            int c4  = (idx & 15) << 2;
            size_t gbase = (size_t)(kt * 64 + row) * QKVC;
            float4 kv = *(const float4*)&qkv[gbase + kcol + c4];
            float4 vv = *(const float4*)&qkv[gbase + vcol + c4];
            float* kd = &Ks[row * ST + c4];
            kd[0] = kv.x; kd[1] = kv.y; kd[2] = kv.z; kd[3] = kv.w;
            float* vd = &Vs[row * ST + c4];
            vd[0] = vv.x; vd[1] = vv.y; vd[2] = vv.z; vd[3] = vv.w;
        }
        __syncthreads();

        // S = Q K^T (4x4 microtile per thread)
        float s[4][4];
#pragma unroll
        for (int i = 0; i < 4; i++)
#pragma unroll
            for (int j = 0; j < 4; j++) s[i][j] = 0.f;

#pragma unroll
        for (int d4 = 0; d4 < 16; d4++) {
            float4 q[4], k[4];
#pragma unroll
            for (int i = 0; i < 4; i++)
                q[i] = *(const float4*)&Qs[(r0 + i) * ST + d4 * 4];
#pragma unroll
            for (int j = 0; j < 4; j++)
                k[j] = *(const float4*)&Ks[(cl + 16 * j) * ST + d4 * 4];
#pragma unroll
            for (int i = 0; i < 4; i++)
#pragma unroll
                for (int j = 0; j < 4; j++)
                    s[i][j] += q[i].x * k[j].x + q[i].y * k[j].y +
                               q[i].z * k[j].z + q[i].w * k[j].w;
        }

        if (kt == qt) {
#pragma unroll
            for (int i = 0; i < 4; i++)
#pragma unroll
                for (int j = 0; j < 4; j++)
                    if (cl + 16 * j > r0 + i) s[i][j] = -INFINITY;
        }

        // Online softmax (row reductions across the 16 lanes sharing rg)
        float alpha[4];
#pragma unroll
        for (int i = 0; i < 4; i++) {
            float mx = fmaxf(fmaxf(s[i][0], s[i][1]), fmaxf(s[i][2], s[i][3]));
#pragma unroll
            for (int off = 1; off < 16; off <<= 1)
                mx = fmaxf(mx, __shfl_xor_sync(0xffffffffu, mx, off));
            float mn = fmaxf(m[i], mx);
            alpha[i] = __expf(m[i] - mn);
            float ps = 0.f;
#pragma unroll
            for (int j = 0; j < 4; j++) {
                s[i][j] = __expf(s[i][j] - mn);
                ps += s[i][j];
            }
#pragma unroll
            for (int off = 1; off < 16; off <<= 1)
                ps += __shfl_xor_sync(0xffffffffu, ps, off);
            l[i] = l[i] * alpha[i] + ps;
            m[i] = mn;
#pragma unroll
            for (int j = 0; j < 4; j++) o[i][j] *= alpha[i];
        }

        __syncthreads();  // everyone done reading Ks before aliasing as Ps
#pragma unroll
        for (int i = 0; i < 4; i++)
#pragma unroll
            for (int j = 0; j < 4; j++)
                Ps[(r0 + i) * ST + cl + 16 * j] = s[i][j];
        __syncthreads();

        // O += P @ V
#pragma unroll 8
        for (int c = 0; c < 64; c++) {
            float4 v = *(const float4*)&Vs[c * ST + cl * 4];
#pragma unroll
            for (int i = 0; i < 4; i++) {
                float p = Ps[(r0 + i) * ST + c];
                o[i][0] = fmaf(p, v.x, o[i][0]);
                o[i][1] = fmaf(p, v.y, o[i][1]);
                o[i][2] = fmaf(p, v.z, o[i][2]);
                o[i][3] = fmaf(p, v.w, o[i][3]);
            }
        }
    }

    // Normalize and write
#pragma unroll
    for (int i = 0; i < 4; i++) {
        float inv = 1.f / l[i];
        float4 v = make_float4(o[i][0] * inv, o[i][1] * inv,
                               o[i][2] * inv, o[i][3] * inv);
        *(float4*)&outp[(size_t)(qt * 64 + r0 + i) * H_ + h * 64 + cl * 4] = v;
    }
}

// ---------------------------------------------------------------------------
extern "C" void kernel_launch(void* const* d_in, const int* in_sizes, int n_in,
                              void* d_out, int out_size)
{
    (void)in_sizes; (void)n_in; (void)out_size;
    const float* x     = (const float*)d_in[0];
    const float* w_qkv = (const float*)d_in[1];
    const float* w_o   = (const float*)d_in[2];
    float* out = (float*)d_out;

    float *qkv, *attn;
    cudaGetSymbolAddress((void**)&qkv,  g_qkv);
    cudaGetSymbolAddress((void**)&attn, g_attn);

    const int attn_smem = 3 * 64 * 68 * (int)sizeof(float);  // 52224 B
    cudaFuncSetAttribute(attn_kernel,
                         cudaFuncAttributeMaxDynamicSharedMemorySize, attn_smem);

    // 1. qkv = x @ w_qkv^T
    dim3 g1(QKVC / 128, S_ / 128);
    gemm_nt<<<g1, 256>>>(x, w_qkv, qkv, S_, QKVC, H_);

    // 2. RoPE on q and k, in place
    int total = S_ * (NH_ + KVH_) * 32;
    rope_kernel<<<(total + 255) / 256, 256>>>(qkv);

    // 3. causal GQA attention
    dim3 ga(NH_, S_ / 64);
    attn_kernel<<<ga, 256, attn_smem>>>(qkv, attn);

    // 4. out = attn @ w_o^T
    dim3 g2(H_ / 128, S_ / 128);
    gemm_nt<<<g2, 256>>>(attn, w_o, out, S_, H_, H_);
}

// round 5
// speedup vs baseline: 1.0004x; 1.0004x over previous
#include <cuda_runtime.h>
#include <math.h>

#define S_    2048
#define H_    2048
#define NH_   32
#define KVH_  8
#define D_    64
#define QKVC  3072   // (NH + 2*KVH) * D

__device__ float g_qkv[S_ * QKVC];   // 24 MiB scratch
__device__ float g_attn[S_ * H_];    // 16 MiB scratch

// ---------------------------------------------------------------------------
// NT GEMM: C[M,N] = A[M,K] @ B[N,K]^T   (both operands K-major, row-major)
// 128x128 block tile, BK=16, 256 threads, 8x8 per-thread microtile.
// ---------------------------------------------------------------------------
__global__ __launch_bounds__(256, 2)
void gemm_nt(const float* __restrict__ A, const float* __restrict__ B,
             float* __restrict__ C, int M, int N, int K)
{
    __shared__ float As[16][128];
    __shared__ float Bs[16][128];

    const int tid = threadIdx.x;
    const int tx  = tid & 15;
    const int ty  = tid >> 4;
    const int m0  = blockIdx.y * 128;
    const int n0  = blockIdx.x * 128;

    const int lr = tid >> 2;          // 0..63
    const int lc = (tid & 3) << 2;    // 0,4,8,12

    float acc[8][8];
#pragma unroll
    for (int i = 0; i < 8; i++)
#pragma unroll
        for (int j = 0; j < 8; j++) acc[i][j] = 0.f;

    const float* Ap = A + (size_t)(m0 + lr) * K + lc;
    const float* Bp = B + (size_t)(n0 + lr) * K + lc;

    for (int k0 = 0; k0 < K; k0 += 16) {
        float4 a0 = *(const float4*)(Ap + k0);
        float4 a1 = *(const float4*)(Ap + (size_t)64 * K + k0);
        float4 b0 = *(const float4*)(Bp + k0);
        float4 b1 = *(const float4*)(Bp + (size_t)64 * K + k0);

        As[lc + 0][lr]      = a0.x; As[lc + 1][lr]      = a0.y;
        As[lc + 2][lr]      = a0.z; As[lc + 3][lr]      = a0.w;
        As[lc + 0][lr + 64] = a1.x; As[lc + 1][lr + 64] = a1.y;
        As[lc + 2][lr + 64] = a1.z; As[lc + 3][lr + 64] = a1.w;

        Bs[lc + 0][lr]      = b0.x; Bs[lc + 1][lr]      = b0.y;
        Bs[lc + 2][lr]      = b0.z; Bs[lc + 3][lr]      = b0.w;
        Bs[lc + 0][lr + 64] = b1.x; Bs[lc + 1][lr + 64] = b1.y;
        Bs[lc + 2][lr + 64] = b1.z; Bs[lc + 3][lr + 64] = b1.w;

        __syncthreads();

#pragma unroll
        for (int kk = 0; kk < 16; kk++) {
            float a[8], b[8];
            *(float4*)&a[0] = *(const float4*)&As[kk][ty * 4];
            *(float4*)&a[4] = *(const float4*)&As[kk][64 + ty * 4];
            *(float4*)&b[0] = *(const float4*)&Bs[kk][tx * 4];
            *(float4*)&b[4] = *(const float4*)&Bs[kk][64 + tx * 4];
#pragma unroll
            for (int i = 0; i < 8; i++)
#pragma unroll
                for (int j = 0; j < 8; j++)
                    acc[i][j] = fmaf(a[i], b[j], acc[i][j]);
        }
        __syncthreads();
    }

#pragma unroll
    for (int ih = 0; ih < 2; ih++)
#pragma unroll
        for (int i = 0; i < 4; i++) {
            int row = m0 + ih * 64 + ty * 4 + i;
            float* Cp = C + (size_t)row * N + n0;
            int ai = ih * 4 + i;
            *(float4*)(Cp + tx * 4) =
                make_float4(acc[ai][0], acc[ai][1], acc[ai][2], acc[ai][3]);
            *(float4*)(Cp + 64 + tx * 4) =
                make_float4(acc[ai][4], acc[ai][5], acc[ai][6], acc[ai][7]);
        }
}

// ---------------------------------------------------------------------------
// RoPE in-place on q (32 heads) and k (8 heads) columns of the qkv buffer.
// ---------------------------------------------------------------------------
__global__ void rope_kernel(float* __restrict__ qkv)
{
    int idx = blockIdx.x * blockDim.x + threadIdx.x;
    const int total = S_ * (NH_ + KVH_) * 32;
    if (idx >= total) return;

    int i  = idx & 31;
    int hh = (idx >> 5) % (NH_ + KVH_);
    int s  = idx / ((NH_ + KVH_) * 32);
    int col = (hh < NH_) ? hh * 64 : NH_ * 64 + (hh - NH_) * 64;

    float inv_freq = powf(10000.0f, -(float)i / 32.0f);
    float fr = (float)s * inv_freq;
    float sn, c;
    sincosf(fr, &sn, &c);

    float* base = qkv + (size_t)s * QKVC + col;
    float x1 = base[i];
    float x2 = base[i + 32];
    base[i]      = x1 * c - x2 * sn;
    base[i + 32] = x2 * c + x1 * sn;
}

// ---------------------------------------------------------------------------
// Flash-style causal GQA attention.
// Grid: (NH heads, S/64 query tiles). Block: 256 threads.
// Thread (rg = tid/16, cl = tid%16) owns score microtile:
//   rows r0..r0+3 (r0 = rg*4), keys {cl + 16j}, output dims {cl*4 + jj}.
// Smem tiles padded to stride 68 (bank-conflict-free row access).
// P tile aliases the K tile.
// ---------------------------------------------------------------------------
__global__ __launch_bounds__(256)
void attn_kernel(const float* __restrict__ qkv, float* __restrict__ outp)
{
    constexpr int ST = 68;
    extern __shared__ float sm[];
    float* Qs = sm;
    float* Ks = sm + 64 * ST;
    float* Vs = sm + 2 * 64 * ST;
    float* Ps = Ks;  // alias

    const int h   = blockIdx.x;
    const int qt  = blockIdx.y;
    const int tid = threadIdx.x;
    const int rg  = tid >> 4;
    const int cl  = tid & 15;
    const int r0  = rg * 4;
    const int kvh = h >> 2;

    const int qcol = h * 64;
    const int kcol = NH_ * 64 + kvh * 64;
    const int vcol = NH_ * 64 + KVH_ * 64 + kvh * 64;

    // Load Q tile (pre-scaled by 1/sqrt(D))
    {
        const float scale = 0.125f;
#pragma unroll
        for (int p = 0; p < 4; p++) {
            int idx = tid + p * 256;
            int row = idx >> 4;
            int c4  = (idx & 15) << 2;
            float4 v = *(const float4*)&qkv[(size_t)(qt * 64 + row) * QKVC + qcol + c4];
            float* dst = &Qs[row * ST + c4];
            dst[0] = v.x * scale; dst[1] = v.y * scale;
            dst[2] = v.z * scale; dst[3] = v.w * scale;
        }
    }

    float m[4], l[4], o[4][4];
#pragma unroll
    for (int i = 0; i < 4; i++) {
        m[i] = -INFINITY; l[i] = 0.f;
#pragma unroll
        for (int j = 0; j < 4; j++) o[i][j] = 0.f;
    }

    for (int kt = 0; kt <= qt; kt++) {
        __syncthreads();  // previous iter done reading Ks(=Ps)/Vs; Q visible on iter 0
#pragma unroll
        for (int p = 0; p < 4; p++) {
            int idx = tid + p * 256;
            int row = idx >> 4;
            int c4  = (idx & 15) << 2;
            size_t gbase = (size_t)(kt * 64 + row) * QKVC;
            float4 kv = *(const float4*)&qkv[gbase + kcol + c4];
            float4 vv = *(const float4*)&qkv[gbase + vcol + c4];
            float* kd = &Ks[row * ST + c4];
            kd[0] = kv.x; kd[1] = kv.y; kd[2] = kv.z; kd[3] = kv.w;
            float* vd = &Vs[row * ST + c4];
            vd[0] = vv.x; vd[1] = vv.y; vd[2] = vv.z; vd[3] = vv.w;
        }
        __syncthreads();

        // S = Q K^T (4x4 microtile per thread)
        float s[4][4];
#pragma unroll
        for (int i = 0; i < 4; i++)
#pragma unroll
            for (int j = 0; j < 4; j++) s[i][j] = 0.f;

#pragma unroll
        for (int d4 = 0; d4 < 16; d4++) {
            float4 q[4], k[4];
#pragma unroll
            for (int i = 0; i < 4; i++)
                q[i] = *(const float4*)&Qs[(r0 + i) * ST + d4 * 4];
#pragma unroll
            for (int j = 0; j < 4; j++)
                k[j] = *(const float4*)&Ks[(cl + 16 * j) * ST + d4 * 4];
#pragma unroll
            for (int i = 0; i < 4; i++)
#pragma unroll
                for (int j = 0; j < 4; j++)
                    s[i][j] += q[i].x * k[j].x + q[i].y * k[j].y +
                               q[i].z * k[j].z + q[i].w * k[j].w;
        }

        if (kt == qt) {
#pragma unroll
            for (int i = 0; i < 4; i++)
#pragma unroll
                for (int j = 0; j < 4; j++)
                    if (cl + 16 * j > r0 + i) s[i][j] = -INFINITY;
        }

        // Online softmax (row reductions across the 16 lanes sharing rg)
        float alpha[4];
#pragma unroll
        for (int i = 0; i < 4; i++) {
            float mx = fmaxf(fmaxf(s[i][0], s[i][1]), fmaxf(s[i][2], s[i][3]));
#pragma unroll
            for (int off = 1; off < 16; off <<= 1)
                mx = fmaxf(mx, __shfl_xor_sync(0xffffffffu, mx, off));
            float mn = fmaxf(m[i], mx);
            alpha[i] = __expf(m[i] - mn);
            float ps = 0.f;
#pragma unroll
            for (int j = 0; j < 4; j++) {
                s[i][j] = __expf(s[i][j] - mn);
                ps += s[i][j];
            }
#pragma unroll
            for (int off = 1; off < 16; off <<= 1)
                ps += __shfl_xor_sync(0xffffffffu, ps, off);
            l[i] = l[i] * alpha[i] + ps;
            m[i] = mn;
#pragma unroll
            for (int j = 0; j < 4; j++) o[i][j] *= alpha[i];
        }

        __syncthreads();  // everyone done reading Ks before aliasing as Ps
#pragma unroll
        for (int i = 0; i < 4; i++)
#pragma unroll
            for (int j = 0; j < 4; j++)
                Ps[(r0 + i) * ST + cl + 16 * j] = s[i][j];
        __syncthreads();

        // O += P @ V
#pragma unroll 8
        for (int c = 0; c < 64; c++) {
            float4 v = *(const float4*)&Vs[c * ST + cl * 4];
#pragma unroll
            for (int i = 0; i < 4; i++) {
                float p = Ps[(r0 + i) * ST + c];
                o[i][0] = fmaf(p, v.x, o[i][0]);
                o[i][1] = fmaf(p, v.y, o[i][1]);
                o[i][2] = fmaf(p, v.z, o[i][2]);
                o[i][3] = fmaf(p, v.w, o[i][3]);
            }
        }
    }

    // Normalize and write
#pragma unroll
    for (int i = 0; i < 4; i++) {
        float inv = 1.f / l[i];
        float4 v = make_float4(o[i][0] * inv, o[i][1] * inv,
                               o[i][2] * inv, o[i][3] * inv);
        *(float4*)&outp[(size_t)(qt * 64 + r0 + i) * H_ + h * 64 + cl * 4] = v;
    }
}

// ---------------------------------------------------------------------------
extern "C" void kernel_launch(void* const* d_in, const int* in_sizes, int n_in,
                              void* d_out, int out_size)
{
    (void)in_sizes; (void)n_in; (void)out_size;
    const float* x     = (const float*)d_in[0];
    const float* w_qkv = (const float*)d_in[1];
    const float* w_o   = (const float*)d_in[2];
    float* out = (float*)d_out;

    float *qkv, *attn;
    cudaGetSymbolAddress((void**)&qkv,  g_qkv);
    cudaGetSymbolAddress((void**)&attn, g_attn);

    const int attn_smem = 3 * 64 * 68 * (int)sizeof(float);  // 52224 B
    cudaFuncSetAttribute(attn_kernel,
                         cudaFuncAttributeMaxDynamicSharedMemorySize, attn_smem);

    // 1. qkv = x @ w_qkv^T
    dim3 g1(QKVC / 128, S_ / 128);
    gemm_nt<<<g1, 256>>>(x, w_qkv, qkv, S_, QKVC, H_);

    // 2. RoPE on q and k, in place
    int total = S_ * (NH_ + KVH_) * 32;
    rope_kernel<<<(total + 255) / 256, 256>>>(qkv);

    // 3. causal GQA attention
    dim3 ga(NH_, S_ / 64);
    attn_kernel<<<ga, 256, attn_smem>>>(qkv, attn);

    // 4. out = attn @ w_o^T
    dim3 g2(H_ / 128, S_ / 128);
    gemm_nt<<<g2, 256>>>(attn, w_o, out, S_, H_, H_);
}